// round 2
// baseline (speedup 1.0000x reference)
#include <cuda_runtime.h>

#define ITEMS 32
#define BLOCK 256
#define CHUNK (ITEMS * BLOCK)   // 8192 samples per block
#define MAXBLKS 65536

// Scratch (no allocation allowed): per-block zero-init end states and incoming states.
__device__ float2 g_blk_end[MAXBLKS];
__device__ float2 g_blk_in[MAXBLKS];

// Affine map s' = M s + v with M lower-triangular: [[m00,0],[m10,m11]]
struct Aff { float m00, m10, m11, v0, v1; };

__device__ __forceinline__ Aff aff_combine(const Aff& B, const Aff& A) {
    // B applied after A:  (B.M*A.M, B.M*A.v + B.v)
    Aff r;
    r.m00 = B.m00 * A.m00;
    r.m10 = fmaf(B.m10, A.m00, B.m11 * A.m10);
    r.m11 = B.m11 * A.m11;
    r.v0  = fmaf(B.m00, A.v0, B.v0);
    r.v1  = fmaf(B.m10, A.v0, fmaf(B.m11, A.v1, B.v1));
    return r;
}

__device__ __forceinline__ float2 aff_apply(const Aff& A, float2 s) {
    float2 r;
    r.x = fmaf(A.m00, s.x, A.v0);
    r.y = fmaf(A.m10, s.x, fmaf(A.m11, s.y, A.v1));
    return r;
}

__device__ __forceinline__ Aff aff_shfl_up(const Aff& a, int d) {
    Aff r;
    r.m00 = __shfl_up_sync(0xffffffffu, a.m00, d);
    r.m10 = __shfl_up_sync(0xffffffffu, a.m10, d);
    r.m11 = __shfl_up_sync(0xffffffffu, a.m11, d);
    r.v0  = __shfl_up_sync(0xffffffffu, a.v0,  d);
    r.v1  = __shfl_up_sync(0xffffffffu, a.v1,  d);
    return r;
}

__device__ __forceinline__ void get_params(const float* __restrict__ p,
                                           float& c1, float& c2,
                                           float& attack, float& decay, float& gain) {
    attack = fmaxf(p[0], 1e-7f);
    decay  = fmaxf(p[1], 1e-7f);
    c1 = fminf(fmaxf(p[2], 1e-7f), 0.99f);   // lowpass coefficient
    c2 = fminf(fmaxf(p[3], 1e-7f), 0.99f);   // highpass coefficient
    gain = fmaxf(p[4], 1e-7f);
}

// Repeated squaring of lower-triangular 2x2
__device__ __forceinline__ void mat_pow2k(float& m00, float& m10, float& m11, int k) {
    #pragma unroll 1
    for (int i = 0; i < k; i++) {
        float n00 = m00 * m00;
        float n10 = m10 * (m00 + m11);
        float n11 = m11 * m11;
        m00 = n00; m10 = n10; m11 = n11;
    }
}

// ---------------------------------------------------------------------------
// Pass 1: per-block zero-initial-state end state
// ---------------------------------------------------------------------------
__global__ void __launch_bounds__(BLOCK)
ng_pass1(const float* __restrict__ params, const float* __restrict__ x, int n) {
    float c1, c2, at, de, g;
    get_params(params, c1, c2, at, de, g);
    const float b1 = 1.0f - c1;

    const int tid = threadIdx.x;
    const long base = (long)blockIdx.x * CHUNK + (long)tid * ITEMS;

    float xv[ITEMS];
    if (base + ITEMS <= n) {
        const float4* xp = (const float4*)(x + base);
        #pragma unroll
        for (int k = 0; k < ITEMS / 4; k++) {
            float4 v = xp[k];
            xv[4*k+0] = v.x; xv[4*k+1] = v.y; xv[4*k+2] = v.z; xv[4*k+3] = v.w;
        }
    } else {
        #pragma unroll
        for (int j = 0; j < ITEMS; j++)
            xv[j] = (base + j < n) ? x[base + j] : 0.0f;
    }

    float y1 = 0.0f, y2 = 0.0f;
    #pragma unroll
    for (int j = 0; j < ITEMS; j++) {
        float y1n = fmaf(c1, y1, b1 * xv[j]);
        y2 = c2 * (y2 + (y1n - y1));
        y1 = y1n;
    }

    // Thread-segment affine: (A^ITEMS, local end state)
    float m00 = c1, m10 = c2 * (c1 - 1.0f), m11 = c2;
    mat_pow2k(m00, m10, m11, 5);            // A^32
    Aff a = {m00, m10, m11, y1, y2};

    const int lane = tid & 31, wid = tid >> 5;
    #pragma unroll
    for (int d = 1; d < 32; d <<= 1) {
        Aff o = aff_shfl_up(a, d);
        if (lane >= d) a = aff_combine(a, o);
    }

    __shared__ Aff wtot[BLOCK / 32];
    if (lane == 31) wtot[wid] = a;
    __syncthreads();
    if (tid == 0) {
        Aff t = wtot[0];
        #pragma unroll
        for (int w = 1; w < BLOCK / 32; w++) t = aff_combine(wtot[w], t);
        g_blk_end[blockIdx.x] = make_float2(t.v0, t.v1);
    }
}

// ---------------------------------------------------------------------------
// Pass 2: exclusive scan of block states (single block, tiled over G)
// ---------------------------------------------------------------------------
__global__ void __launch_bounds__(512)
ng_pass2(const float* __restrict__ params, int G) {
    float c1, c2, at, de, g;
    get_params(params, c1, c2, at, de, g);
    float q00 = c1, q10 = c2 * (c1 - 1.0f), q11 = c2;
    mat_pow2k(q00, q10, q11, 13);           // A^8192 = A^CHUNK

    const int tid = threadIdx.x, lane = tid & 31, wid = tid >> 5;
    __shared__ Aff   wtot[16];
    __shared__ float2 win[16];
    __shared__ float2 carry_sh;

    float2 carry = make_float2(0.0f, 0.0f);
    for (int basei = 0; basei < G; basei += 512) {
        int t = basei + tid;
        float2 ve = (t < G) ? g_blk_end[t] : make_float2(0.0f, 0.0f);
        Aff a = {q00, q10, q11, ve.x, ve.y};
        #pragma unroll
        for (int d = 1; d < 32; d <<= 1) {
            Aff o = aff_shfl_up(a, d);
            if (lane >= d) a = aff_combine(a, o);
        }
        if (lane == 31) wtot[wid] = a;
        __syncthreads();
        if (tid == 0) {
            float2 s = carry;
            #pragma unroll
            for (int w = 0; w < 16; w++) { win[w] = s; s = aff_apply(wtot[w], s); }
            carry_sh = s;
        }
        __syncthreads();
        Aff sh = aff_shfl_up(a, 1);
        Aff ex;
        if (lane == 0) { ex.m00 = 1.f; ex.m10 = 0.f; ex.m11 = 1.f; ex.v0 = 0.f; ex.v1 = 0.f; }
        else ex = sh;
        float2 sin = aff_apply(ex, win[wid]);
        if (t < G) g_blk_in[t] = sin;
        carry = carry_sh;
        __syncthreads();
    }
}

// ---------------------------------------------------------------------------
// Pass 3: seeded replay + fused envelope (geometric-sequence exp) + store
// ---------------------------------------------------------------------------
__global__ void __launch_bounds__(BLOCK)
ng_pass3(const float* __restrict__ params, const float* __restrict__ x,
         float* __restrict__ out, int n) {
    float c1, c2, at, de, g;
    get_params(params, c1, c2, at, de, g);
    const float b1 = 1.0f - c1;

    const int tid = threadIdx.x;
    const long base = (long)blockIdx.x * CHUNK + (long)tid * ITEMS;
    const bool full = (base + ITEMS) <= n;

    float xv[ITEMS];
    if (full) {
        const float4* xp = (const float4*)(x + base);
        #pragma unroll
        for (int k = 0; k < ITEMS / 4; k++) {
            float4 v = xp[k];
            xv[4*k+0] = v.x; xv[4*k+1] = v.y; xv[4*k+2] = v.z; xv[4*k+3] = v.w;
        }
    } else {
        #pragma unroll
        for (int j = 0; j < ITEMS; j++)
            xv[j] = (base + j < n) ? x[base + j] : 0.0f;
    }

    // Local zero-state sweep to form scan input
    float y1 = 0.0f, y2 = 0.0f;
    #pragma unroll
    for (int j = 0; j < ITEMS; j++) {
        float y1n = fmaf(c1, y1, b1 * xv[j]);
        y2 = c2 * (y2 + (y1n - y1));
        y1 = y1n;
    }

    float m00 = c1, m10 = c2 * (c1 - 1.0f), m11 = c2;
    mat_pow2k(m00, m10, m11, 5);            // A^32
    Aff a = {m00, m10, m11, y1, y2};

    const int lane = tid & 31, wid = tid >> 5;
    #pragma unroll
    for (int d = 1; d < 32; d <<= 1) {
        Aff o = aff_shfl_up(a, d);
        if (lane >= d) a = aff_combine(a, o);
    }

    __shared__ Aff   wtot[BLOCK / 32];
    __shared__ float2 win[BLOCK / 32];
    if (lane == 31) wtot[wid] = a;
    __syncthreads();
    if (tid == 0) {
        float2 s = g_blk_in[blockIdx.x];
        #pragma unroll
        for (int w = 0; w < BLOCK / 32; w++) { win[w] = s; s = aff_apply(wtot[w], s); }
    }
    __syncthreads();

    Aff sh = aff_shfl_up(a, 1);
    Aff ex;
    if (lane == 0) { ex.m00 = 1.f; ex.m10 = 0.f; ex.m11 = 1.f; ex.v0 = 0.f; ex.v1 = 0.f; }
    else ex = sh;
    float2 s0 = aff_apply(ex, win[wid]);

    // Envelope: env(t)*gain = gain*(exp(-t*k1) - exp(-t*k2)); geometric per-sample update.
    const float inv_n1 = 1.0f / (float)(n - 1);
    const float k1 = 1.0f / de;
    const float k2 = 1.0f / at + k1;
    const float t0 = (float)base * inv_n1;
    float e1 = g * __expf(-t0 * k1);
    float e2 = g * __expf(-t0 * k2);
    const float r1 = __expf(-inv_n1 * k1);
    const float r2 = __expf(-inv_n1 * k2);

    y1 = s0.x; y2 = s0.y;
    if (full) {
        float4* op = (float4*)(out + base);
        #pragma unroll
        for (int k = 0; k < ITEMS / 4; k++) {
            float4 o;
            #pragma unroll
            for (int q = 0; q < 4; q++) {
                float xn = xv[4*k + q];
                float y1n = fmaf(c1, y1, b1 * xn);
                y2 = c2 * (y2 + (y1n - y1));
                y1 = y1n;
                float v = y2 * (e1 - e2);
                e1 *= r1; e2 *= r2;
                if (q == 0) o.x = v; else if (q == 1) o.y = v;
                else if (q == 2) o.z = v; else o.w = v;
            }
            op[k] = o;
        }
    } else {
        #pragma unroll
        for (int j = 0; j < ITEMS; j++) {
            float y1n = fmaf(c1, y1, b1 * xv[j]);
            y2 = c2 * (y2 + (y1n - y1));
            y1 = y1n;
            float v = y2 * (e1 - e2);
            e1 *= r1; e2 *= r2;
            if (base + j < n) out[base + j] = v;
        }
    }
}

// ---------------------------------------------------------------------------
extern "C" void kernel_launch(void* const* d_in, const int* in_sizes, int n_in,
                              void* d_out, int out_size) {
    int i_par = 0, i_noise = 1;
    if (n_in >= 2 && in_sizes[0] > in_sizes[1]) { i_par = 1; i_noise = 0; }
    const float* params = (const float*)d_in[i_par];
    const float* noise  = (const float*)d_in[i_noise];
    float* out = (float*)d_out;
    const int n = in_sizes[i_noise];
    int G = (n + CHUNK - 1) / CHUNK;
    if (G > MAXBLKS) G = MAXBLKS;  // problem size is 2^22 -> G = 512

    ng_pass1<<<G, BLOCK>>>(params, noise, n);
    ng_pass2<<<1, 512>>>(params, G);
    ng_pass3<<<G, BLOCK>>>(params, noise, out, n);
}